// round 1
// baseline (speedup 1.0000x reference)
#include <cuda_runtime.h>

#define BATCH   64
#define NATOMS  64
#define HDIM    256
#define ROWS_TOT (2 * BATCH * NATOMS)   /* 8192 */
#define JCHUNK  16
#define NCHUNK  (NATOMS / JCHUNK)       /* 4 */

/* scratch: s1 rows [0,4096), s2 rows [4096,8192) */
__device__ float g_s[ROWS_TOT * HDIM];                     /* 8 MB */
__device__ float g_rpart[BATCH * NCHUNK * NATOMS];
__device__ float g_c[BATCH * NATOMS];

__device__ __forceinline__ float fast_tanh(float x) {
    float y; asm("tanh.approx.f32 %0, %1;" : "=f"(y) : "f"(x)); return y;
}

/* ---------------- GEMM: g_s = [h1 @ W1[:256] + b1 ; h2 @ W1[256:]] ------- */
__global__ void __launch_bounds__(256) gemm_kernel(
    const float* __restrict__ h1, const float* __restrict__ h2,
    const float* __restrict__ W1, const float* __restrict__ b1)
{
    const int KC = 32;
    __shared__ float As[KC][64];     /* [k][row] */
    __shared__ float Bs[KC][HDIM];   /* [k][n]   */

    int row0 = blockIdx.x * 64;
    bool second = (row0 >= BATCH * NATOMS);
    const float* A = second ? (h2 + (row0 - BATCH * NATOMS) * HDIM)
                            : (h1 + row0 * HDIM);
    const float* W = W1 + (second ? HDIM * HDIM : 0);

    int tid = threadIdx.x;
    int tx = tid & 31, ty = tid >> 5;

    float acc[8][8];
#pragma unroll
    for (int r = 0; r < 8; r++)
#pragma unroll
        for (int c = 0; c < 8; c++) acc[r][c] = 0.f;

    for (int kc = 0; kc < HDIM; kc += KC) {
        /* A chunk: 64 rows x 32 k  (512 float4, 2/thread) */
#pragma unroll
        for (int l = 0; l < 2; l++) {
            int f = tid + l * 256;
            int row = f >> 3;
            int c4  = f & 7;
            float4 v = *(const float4*)(A + row * HDIM + kc + c4 * 4);
            As[c4 * 4 + 0][row] = v.x;
            As[c4 * 4 + 1][row] = v.y;
            As[c4 * 4 + 2][row] = v.z;
            As[c4 * 4 + 3][row] = v.w;
        }
        /* B chunk: 32 k x 256 n  (2048 float4, 8/thread) */
#pragma unroll
        for (int l = 0; l < 8; l++) {
            int f = tid + l * 256;
            int k  = f >> 6;
            int n4 = f & 63;
            *(float4*)&Bs[k][n4 * 4] = *(const float4*)(W + (kc + k) * HDIM + n4 * 4);
        }
        __syncthreads();

#pragma unroll
        for (int k = 0; k < KC; k++) {
            float a[8], bb[8];
            *(float4*)&a[0]  = *(float4*)&As[k][ty * 8];
            *(float4*)&a[4]  = *(float4*)&As[k][ty * 8 + 4];
            *(float4*)&bb[0] = *(float4*)&Bs[k][tx * 8];
            *(float4*)&bb[4] = *(float4*)&Bs[k][tx * 8 + 4];
#pragma unroll
            for (int r = 0; r < 8; r++)
#pragma unroll
                for (int c = 0; c < 8; c++)
                    acc[r][c] = fmaf(a[r], bb[c], acc[r][c]);
        }
        __syncthreads();
    }

    /* epilogue: +b1 for the s1 half only (b1 applied once overall) */
    float4 bias0 = make_float4(0.f, 0.f, 0.f, 0.f), bias1 = bias0;
    if (!second) {
        bias0 = *(const float4*)(b1 + tx * 8);
        bias1 = *(const float4*)(b1 + tx * 8 + 4);
    }
#pragma unroll
    for (int r = 0; r < 8; r++) {
        int row = row0 + ty * 8 + r;
        float* out = g_s + row * HDIM + tx * 8;
        float4 v0 = make_float4(acc[r][0] + bias0.x, acc[r][1] + bias0.y,
                                acc[r][2] + bias0.z, acc[r][3] + bias0.w);
        float4 v1 = make_float4(acc[r][4] + bias1.x, acc[r][5] + bias1.y,
                                acc[r][6] + bias1.z, acc[r][7] + bias1.w);
        *(float4*)(out)     = v0;
        *(float4*)(out + 4) = v1;
    }
}

/* -------- fused score + exp + row/col partial sums (no max needed) ------- */
__global__ void __launch_bounds__(256) score_kernel(const float* __restrict__ W2)
{
    __shared__ float s2s[JCHUNK * HDIM];   /* 16 KB */
    __shared__ float colbuf[8][JCHUNK];

    int b  = blockIdx.y;
    int jc = blockIdx.x;
    int tid = threadIdx.x, lane = tid & 31, w = tid >> 5;

    /* stage the 16 s2 rows for this chunk */
    const float* s2g = g_s + (BATCH * NATOMS + b * NATOMS + jc * JCHUNK) * HDIM;
#pragma unroll
    for (int l = 0; l < 4; l++) {
        int f = tid + l * 256;             /* float4 index 0..1023 */
        *(float4*)&s2s[f * 4] = *(const float4*)(s2g + f * 4);
    }
    __syncthreads();

    float wv[8];
    *(float4*)&wv[0] = *(const float4*)(W2 + lane * 8);
    *(float4*)&wv[4] = *(const float4*)(W2 + lane * 8 + 4);

    float colacc = 0.f;
    const float* s1g = g_s + (b * NATOMS) * HDIM;

#pragma unroll 1
    for (int r = 0; r < 8; r++) {
        int i = w * 8 + r;
        float a[8];
        *(float4*)&a[0] = *(const float4*)(s1g + i * HDIM + lane * 8);
        *(float4*)&a[4] = *(const float4*)(s1g + i * HDIM + lane * 8 + 4);
        float rowacc = 0.f;
#pragma unroll
        for (int j = 0; j < JCHUNK; j++) {
            float bb[8];
            *(float4*)&bb[0] = *(float4*)&s2s[j * HDIM + lane * 8];
            *(float4*)&bb[4] = *(float4*)&s2s[j * HDIM + lane * 8 + 4];
            float p = 0.f;
#pragma unroll
            for (int t = 0; t < 8; t++)
                p = fmaf(wv[t], fast_tanh(a[t] + bb[t]), p);
#pragma unroll
            for (int o = 16; o > 0; o >>= 1)
                p += __shfl_xor_sync(0xffffffffu, p, o);
            float e = __expf(p);           /* scores bounded: no max pass */
            rowacc += e;
            if (lane == j) colacc += e;
        }
        if (lane == 0)
            g_rpart[(b * NCHUNK + jc) * NATOMS + i] = rowacc;
    }
    if (lane < JCHUNK) colbuf[w][lane] = colacc;
    __syncthreads();
    if (tid < JCHUNK) {
        float s = 0.f;
#pragma unroll
        for (int ww = 0; ww < 8; ww++) s += colbuf[ww][tid];
        g_c[b * NATOMS + jc * JCHUNK + tid] = s;
    }
}

/* ---------------- normalize: att1 = r/Z, att2 = c/Z ---------------------- */
__global__ void __launch_bounds__(64) finalize_kernel(float* __restrict__ out)
{
    int b = blockIdx.x, i = threadIdx.x;
    float r = 0.f;
#pragma unroll
    for (int c = 0; c < NCHUNK; c++)
        r += g_rpart[(b * NCHUNK + c) * NATOMS + i];

    __shared__ float red[64];
    red[i] = r;
    __syncthreads();
    if (i < 32) {
        float v = red[i] + red[i + 32];
#pragma unroll
        for (int o = 16; o > 0; o >>= 1)
            v += __shfl_xor_sync(0xffffffffu, v, o);
        if (i == 0) red[0] = v;
    }
    __syncthreads();
    float inv = 1.f / red[0];
    out[b * NATOMS + i] = r * inv;
    out[BATCH * NATOMS + b * NATOMS + i] = g_c[b * NATOMS + i] * inv;
}

extern "C" void kernel_launch(void* const* d_in, const int* in_sizes, int n_in,
                              void* d_out, int out_size)
{
    /* locate tensors by element count (robust to scalar-arg handling):
       1048576 -> h1 then h2; 131072 -> W1; 256 -> b1 then W2 */
    const float *h1 = nullptr, *h2 = nullptr, *W1 = nullptr,
                *b1 = nullptr, *W2 = nullptr;
    for (int idx = 0; idx < n_in; idx++) {
        int sz = in_sizes[idx];
        if (sz == BATCH * NATOMS * HDIM) {
            if (!h1) h1 = (const float*)d_in[idx];
            else if (!h2) h2 = (const float*)d_in[idx];
        } else if (sz == 2 * HDIM * HDIM) {
            W1 = (const float*)d_in[idx];
        } else if (sz == HDIM) {
            if (!b1) b1 = (const float*)d_in[idx];
            else if (!W2) W2 = (const float*)d_in[idx];
        }
    }
    float* out = (float*)d_out;

    gemm_kernel<<<ROWS_TOT / 64, 256>>>(h1, h2, W1, b1);
    score_kernel<<<dim3(NCHUNK, BATCH), 256>>>(W2);
    finalize_kernel<<<BATCH, 64>>>(out);
}

// round 2
// speedup vs baseline: 1.5677x; 1.5677x over previous
#include <cuda_runtime.h>
#include <cuda_fp16.h>

#define BATCH   64
#define NATOMS  64
#define HDIM    256
#define NROWS   (2 * BATCH * NATOMS)   /* 8192 */
#define H2      (HDIM / 2)             /* 128 half2 per row */

/* s = [h1@W1[:H]+b1 ; h2@W1[H:]] stored as packed half2 (4 MB) */
__device__ unsigned g_sh[NROWS * H2];
__device__ float g_rp[BATCH * NATOMS * 2];   /* row partials, 2 j-halves */
__device__ float g_cp[BATCH * NATOMS * 2];   /* col partials, 2 i-halves */

__device__ __forceinline__ unsigned f2tf32(float x) {
    unsigned r; asm("cvt.rna.tf32.f32 %0, %1;" : "=r"(r) : "f"(x)); return r;
}
__device__ __forceinline__ unsigned pack_h2(float x, float y) {
    __half2 h = __floats2half2_rn(x, y);
    return *reinterpret_cast<unsigned*>(&h);
}
__device__ __forceinline__ unsigned tanh2u(unsigned x) {
    unsigned y; asm("tanh.approx.f16x2 %0, %1;" : "=r"(y) : "r"(x)); return y;
}
__device__ __forceinline__ __half2 u2h(unsigned u) {
    return *reinterpret_cast<__half2*>(&u);
}
__device__ __forceinline__ unsigned hadd2u(unsigned a, unsigned b) {
    __half2 r = __hadd2(u2h(a), u2h(b));
    return *reinterpret_cast<unsigned*>(&r);
}

/* ============== tf32 tensor-core GEMM: 64x64 tile per CTA =============== */
__global__ void __launch_bounds__(128) gemm_kernel(
    const float* __restrict__ h1, const float* __restrict__ h2,
    const float* __restrict__ W1, const float* __restrict__ b1)
{
    __shared__ unsigned As[64 * 36];   /* [row][k] pad 32->36: conflict-free frags */
    __shared__ unsigned Bs[32 * 72];   /* [k][n]   pad 64->72: conflict-free frags */

    const int row0 = blockIdx.x * 64;
    const int n0   = blockIdx.y * 64;
    const bool second = (row0 >= BATCH * NATOMS);
    const float* A = second ? h2 + (row0 - BATCH * NATOMS) * HDIM
                            : h1 + row0 * HDIM;
    const float* W = W1 + (second ? HDIM * HDIM : 0);

    const int tid = threadIdx.x;
    const int lane = tid & 31, w = tid >> 5;
    const int wm = w >> 1, wn = w & 1;        /* 2x2 warp grid over 64x64 */
    const int gid = lane >> 2, tig = lane & 3;

    float acc[2][4][4];
#pragma unroll
    for (int mt = 0; mt < 2; mt++)
#pragma unroll
        for (int nt = 0; nt < 4; nt++)
#pragma unroll
            for (int q = 0; q < 4; q++) acc[mt][nt][q] = 0.f;

    for (int kc = 0; kc < HDIM; kc += 32) {
        /* stage A: 64 rows x 32 k (512 float4) with tf32 convert */
#pragma unroll
        for (int l = 0; l < 4; l++) {
            int f = tid + l * 128;
            int r = f >> 3, c4 = f & 7;
            float4 v = *(const float4*)(A + r * HDIM + kc + c4 * 4);
            uint4 t = make_uint4(f2tf32(v.x), f2tf32(v.y), f2tf32(v.z), f2tf32(v.w));
            *(uint4*)&As[r * 36 + c4 * 4] = t;
        }
        /* stage B: 32 k x 64 n (512 float4) */
#pragma unroll
        for (int l = 0; l < 4; l++) {
            int f = tid + l * 128;
            int k = f >> 4, n4 = f & 15;
            float4 v = *(const float4*)(W + (kc + k) * HDIM + n0 + n4 * 4);
            uint4 t = make_uint4(f2tf32(v.x), f2tf32(v.y), f2tf32(v.z), f2tf32(v.w));
            *(uint4*)&Bs[k * 72 + n4 * 4] = t;
        }
        __syncthreads();

#pragma unroll
        for (int ks = 0; ks < 4; ks++) {
            unsigned a[2][4], bfr[4][2];
#pragma unroll
            for (int mt = 0; mt < 2; mt++) {
                int r = wm * 32 + mt * 16 + gid;
                int kk = ks * 8 + tig;
                a[mt][0] = As[r * 36 + kk];
                a[mt][1] = As[(r + 8) * 36 + kk];
                a[mt][2] = As[r * 36 + kk + 4];
                a[mt][3] = As[(r + 8) * 36 + kk + 4];
            }
#pragma unroll
            for (int nt = 0; nt < 4; nt++) {
                int c = wn * 32 + nt * 8 + gid;
                bfr[nt][0] = Bs[(ks * 8 + tig) * 72 + c];
                bfr[nt][1] = Bs[(ks * 8 + tig + 4) * 72 + c];
            }
#pragma unroll
            for (int mt = 0; mt < 2; mt++)
#pragma unroll
                for (int nt = 0; nt < 4; nt++)
                    asm volatile(
                        "mma.sync.aligned.m16n8k8.row.col.f32.tf32.tf32.f32 "
                        "{%0,%1,%2,%3}, {%4,%5,%6,%7}, {%8,%9}, {%0,%1,%2,%3};"
                        : "+f"(acc[mt][nt][0]), "+f"(acc[mt][nt][1]),
                          "+f"(acc[mt][nt][2]), "+f"(acc[mt][nt][3])
                        : "r"(a[mt][0]), "r"(a[mt][1]), "r"(a[mt][2]), "r"(a[mt][3]),
                          "r"(bfr[nt][0]), "r"(bfr[nt][1]));
        }
        __syncthreads();
    }

    /* epilogue: +b1 (first half only), pack to half2, store */
#pragma unroll
    for (int mt = 0; mt < 2; mt++) {
        int r = row0 + wm * 32 + mt * 16 + gid;
#pragma unroll
        for (int nt = 0; nt < 4; nt++) {
            int col = n0 + wn * 32 + nt * 8 + tig * 2;
            float bx = 0.f, by = 0.f;
            if (!second) { float2 bv = *(const float2*)(b1 + col); bx = bv.x; by = bv.y; }
            g_sh[r * H2 + (col >> 1)]       = pack_h2(acc[mt][nt][0] + bx, acc[mt][nt][1] + by);
            g_sh[(r + 8) * H2 + (col >> 1)] = pack_h2(acc[mt][nt][2] + bx, acc[mt][nt][3] + by);
        }
    }
}

/* ====== fused score: tanh.f16x2 + exp, fp32 dot accumulation ====== */
__global__ void __launch_bounds__(256) score_kernel(const float* __restrict__ W2)
{
    __shared__ unsigned s1s[32 * 128];   /* [i][hh] half2 */
    __shared__ unsigned s2s[32 * 129];   /* [j][hh] half2, pad -> conflict-free */
    __shared__ float2   w2s[128];
    __shared__ float    colbuf[8][32];

    const int jh = blockIdx.x, ih = blockIdx.y, b = blockIdx.z;
    const int tid = threadIdx.x, lane = tid & 31, w = tid >> 5;

    if (tid < 128) w2s[tid] = *(const float2*)(W2 + tid * 2);

    const unsigned* s1g = g_sh + (b * NATOMS + ih * 32) * H2;
#pragma unroll
    for (int l = 0; l < 4; l++) {
        int f = tid + l * 256;                       /* uint4 index */
        *(uint4*)&s1s[f * 4] = *(const uint4*)(s1g + f * 4);
    }
    const unsigned* s2g = g_sh + (BATCH * NATOMS + b * NATOMS + jh * 32) * H2;
#pragma unroll
    for (int l = 0; l < 4; l++) {
        int f = tid + l * 256;
        int j = f >> 5, q = f & 31;
        uint4 v = *(const uint4*)(s2g + f * 4);
        unsigned* d = &s2s[j * 129 + q * 4];
        d[0] = v.x; d[1] = v.y; d[2] = v.z; d[3] = v.w;
    }
    __syncthreads();

    /* warp w handles i rows [w*4, w*4+4), lane = local j */
    const unsigned* s2row = &s2s[lane * 129];
    float accA[4], accB[4];
#pragma unroll
    for (int ii = 0; ii < 4; ii++) { accA[ii] = 0.f; accB[ii] = 0.f; }

#pragma unroll 4
    for (int hh = 0; hh < 128; hh++) {
        float2 wv = w2s[hh];           /* broadcast */
        unsigned b2 = s2row[hh];       /* conflict-free */
#pragma unroll
        for (int ii = 0; ii < 4; ii++) {
            unsigned a2 = s1s[(w * 4 + ii) * 128 + hh];   /* broadcast */
            unsigned th = tanh2u(hadd2u(a2, b2));
            float2 tf = __half22float2(u2h(th));
            accA[ii] = fmaf(wv.x, tf.x, accA[ii]);
            accB[ii] = fmaf(wv.y, tf.y, accB[ii]);
        }
    }

    float colacc = 0.f;
#pragma unroll
    for (int ii = 0; ii < 4; ii++) {
        float score = accA[ii] + accB[ii];   /* b2 bias cancels in softmax */
        float e = __expf(score);             /* bounded scores: no max pass */
        colacc += e;
        float rs = e;
#pragma unroll
        for (int o = 16; o > 0; o >>= 1)
            rs += __shfl_xor_sync(0xffffffffu, rs, o);
        if (lane == 0)
            g_rp[(b * NATOMS + ih * 32 + w * 4 + ii) * 2 + jh] = rs;
    }
    colbuf[w][lane] = colacc;
    __syncthreads();
    if (tid < 32) {
        float s = 0.f;
#pragma unroll
        for (int ww = 0; ww < 8; ww++) s += colbuf[ww][tid];
        g_cp[(b * NATOMS + jh * 32 + tid) * 2 + ih] = s;
    }
}

/* ---------------- normalize ---------------- */
__global__ void __launch_bounds__(64) finalize_kernel(float* __restrict__ out)
{
    int b = blockIdx.x, i = threadIdx.x;
    float r = g_rp[(b * 64 + i) * 2] + g_rp[(b * 64 + i) * 2 + 1];
    float c = g_cp[(b * 64 + i) * 2] + g_cp[(b * 64 + i) * 2 + 1];
    __shared__ float red[64];
    red[i] = r;
    __syncthreads();
    if (i < 32) {
        float v = red[i] + red[i + 32];
#pragma unroll
        for (int o = 16; o > 0; o >>= 1)
            v += __shfl_xor_sync(0xffffffffu, v, o);
        if (i == 0) red[0] = v;
    }
    __syncthreads();
    float inv = 1.f / red[0];
    out[b * 64 + i] = r * inv;
    out[BATCH * NATOMS + b * 64 + i] = c * inv;
}

extern "C" void kernel_launch(void* const* d_in, const int* in_sizes, int n_in,
                              void* d_out, int out_size)
{
    const float *h1 = nullptr, *h2 = nullptr, *W1 = nullptr,
                *b1 = nullptr, *W2 = nullptr;
    for (int idx = 0; idx < n_in; idx++) {
        int sz = in_sizes[idx];
        if (sz == BATCH * NATOMS * HDIM) {
            if (!h1) h1 = (const float*)d_in[idx];
            else if (!h2) h2 = (const float*)d_in[idx];
        } else if (sz == 2 * HDIM * HDIM) {
            W1 = (const float*)d_in[idx];
        } else if (sz == HDIM) {
            if (!b1) b1 = (const float*)d_in[idx];
            else if (!W2) W2 = (const float*)d_in[idx];
        }
    }
    float* out = (float*)d_out;

    gemm_kernel<<<dim3(NROWS / 64, HDIM / 64), 128>>>(h1, h2, W1, b1);
    score_kernel<<<dim3(2, 2, BATCH), 256>>>(W2);
    finalize_kernel<<<BATCH, 64>>>(out);
}

// round 3
// speedup vs baseline: 1.6545x; 1.0553x over previous
#include <cuda_runtime.h>
#include <cuda_fp16.h>

#define BATCH   64
#define NATOMS  64
#define HDIM    256
#define NROWS   (2 * BATCH * NATOMS)   /* 8192 */
#define H2      (HDIM / 2)             /* 128 half2 per row */

/* s = [h1@W1[:H]+b1 ; h2@W1[H:]] packed half2 (4 MB) */
__device__ unsigned g_sh[NROWS * H2];
__device__ float g_rp[BATCH * NATOMS * 2];   /* row partials, 2 j-halves  */
__device__ float g_cp[BATCH * NATOMS * 4];   /* col partials, 4 i-quarters */

__device__ __forceinline__ unsigned pack_h2(float x, float y) {
    __half2 h = __floats2half2_rn(x, y);
    return *reinterpret_cast<unsigned*>(&h);
}
__device__ __forceinline__ unsigned tanh2u(unsigned x) {
    unsigned y; asm("tanh.approx.f16x2 %0, %1;" : "=r"(y) : "r"(x)); return y;
}
__device__ __forceinline__ __half2 u2h(unsigned u) {
    return *reinterpret_cast<__half2*>(&u);
}
__device__ __forceinline__ unsigned hadd2u(unsigned a, unsigned b) {
    __half2 r = __hadd2(u2h(a), u2h(b));
    return *reinterpret_cast<unsigned*>(&r);
}
__device__ __forceinline__ void cp_async16(void* smem, const void* gmem) {
    unsigned s = (unsigned)__cvta_generic_to_shared(smem);
    asm volatile("cp.async.cg.shared.global [%0], [%1], 16;" :: "r"(s), "l"(gmem));
}

/* ===== tf32 tensor GEMM, 64x64 tile, 2-stage cp.async pipeline ===== */
__global__ void __launch_bounds__(128) gemm_kernel(
    const float* __restrict__ h1, const float* __restrict__ h2,
    const float* __restrict__ W1, const float* __restrict__ b1)
{
    __shared__ float As[2][64 * 36];   /* [row][k], pad 36 -> conflict-free */
    __shared__ float Bs[2][32 * 72];   /* [k][n],   pad 72 -> conflict-free */

    const int row0 = blockIdx.x * 64;
    const int n0   = blockIdx.y * 64;
    const bool second = (row0 >= BATCH * NATOMS);
    const float* A = second ? h2 + (row0 - BATCH * NATOMS) * HDIM
                            : h1 + row0 * HDIM;
    const float* W = W1 + (second ? HDIM * HDIM : 0);

    const int tid = threadIdx.x;
    const int lane = tid & 31, w = tid >> 5;
    const int wm = w >> 1, wn = w & 1;
    const int gid = lane >> 2, tig = lane & 3;

    /* staging index precompute (4 x A-float4, 4 x B-float4 per thread) */
    int ar[4], ac[4], bk[4], bn[4];
#pragma unroll
    for (int l = 0; l < 4; l++) {
        int f = tid + l * 128;
        ar[l] = f >> 3;  ac[l] = f & 7;
        bk[l] = f >> 4;  bn[l] = f & 15;
    }

    float acc[2][4][4];
#pragma unroll
    for (int mt = 0; mt < 2; mt++)
#pragma unroll
        for (int nt = 0; nt < 4; nt++)
#pragma unroll
            for (int q = 0; q < 4; q++) acc[mt][nt][q] = 0.f;

    /* prologue: stage k-chunk 0 */
#pragma unroll
    for (int l = 0; l < 4; l++)
        cp_async16(&As[0][ar[l] * 36 + ac[l] * 4], A + ar[l] * HDIM + ac[l] * 4);
#pragma unroll
    for (int l = 0; l < 4; l++)
        cp_async16(&Bs[0][bk[l] * 72 + bn[l] * 4], W + bk[l] * HDIM + n0 + bn[l] * 4);
    asm volatile("cp.async.commit_group;");

    for (int kci = 0; kci < 8; kci++) {
        const int s = kci & 1;
        if (kci + 1 < 8) {
            const int kc = (kci + 1) * 32;
#pragma unroll
            for (int l = 0; l < 4; l++)
                cp_async16(&As[s ^ 1][ar[l] * 36 + ac[l] * 4],
                           A + ar[l] * HDIM + kc + ac[l] * 4);
#pragma unroll
            for (int l = 0; l < 4; l++)
                cp_async16(&Bs[s ^ 1][bk[l] * 72 + bn[l] * 4],
                           W + (kc + bk[l]) * HDIM + n0 + bn[l] * 4);
            asm volatile("cp.async.commit_group;");
            asm volatile("cp.async.wait_group 1;");
        } else {
            asm volatile("cp.async.wait_group 0;");
        }
        __syncthreads();

        const unsigned* Au = (const unsigned*)As[s];
        const unsigned* Bu = (const unsigned*)Bs[s];
#pragma unroll
        for (int ks = 0; ks < 4; ks++) {
            unsigned a[2][4], bfr[4][2];
#pragma unroll
            for (int mt = 0; mt < 2; mt++) {
                int r = wm * 32 + mt * 16 + gid;
                int kk = ks * 8 + tig;
                a[mt][0] = Au[r * 36 + kk];
                a[mt][1] = Au[(r + 8) * 36 + kk];
                a[mt][2] = Au[r * 36 + kk + 4];
                a[mt][3] = Au[(r + 8) * 36 + kk + 4];
            }
#pragma unroll
            for (int nt = 0; nt < 4; nt++) {
                int c = wn * 32 + nt * 8 + gid;
                bfr[nt][0] = Bu[(ks * 8 + tig) * 72 + c];
                bfr[nt][1] = Bu[(ks * 8 + tig + 4) * 72 + c];
            }
#pragma unroll
            for (int mt = 0; mt < 2; mt++)
#pragma unroll
                for (int nt = 0; nt < 4; nt++)
                    asm volatile(
                        "mma.sync.aligned.m16n8k8.row.col.f32.tf32.tf32.f32 "
                        "{%0,%1,%2,%3}, {%4,%5,%6,%7}, {%8,%9}, {%0,%1,%2,%3};"
                        : "+f"(acc[mt][nt][0]), "+f"(acc[mt][nt][1]),
                          "+f"(acc[mt][nt][2]), "+f"(acc[mt][nt][3])
                        : "r"(a[mt][0]), "r"(a[mt][1]), "r"(a[mt][2]), "r"(a[mt][3]),
                          "r"(bfr[nt][0]), "r"(bfr[nt][1]));
        }
        __syncthreads();
    }

    /* epilogue: +b1 (first half only), pack half2, store */
#pragma unroll
    for (int mt = 0; mt < 2; mt++) {
        int r = row0 + wm * 32 + mt * 16 + gid;
#pragma unroll
        for (int nt = 0; nt < 4; nt++) {
            int col = n0 + wn * 32 + nt * 8 + tig * 2;
            float bx = 0.f, by = 0.f;
            if (!second) { float2 bv = *(const float2*)(b1 + col); bx = bv.x; by = bv.y; }
            g_sh[r * H2 + (col >> 1)]       = pack_h2(acc[mt][nt][0] + bx, acc[mt][nt][1] + by);
            g_sh[(r + 8) * H2 + (col >> 1)] = pack_h2(acc[mt][nt][2] + bx, acc[mt][nt][3] + by);
        }
    }
}

/* ===== fused score: tanh.f16x2 + exp, fp32 accumulation, 16i x 32j ===== */
__global__ void __launch_bounds__(256) score_kernel(const float* __restrict__ W2)
{
    __shared__ unsigned s1s[16 * 128];    /* [i][hh] half2                 */
    __shared__ unsigned s2s[32 * 130];    /* [j][hh] half2, pad 130: LDS.64 ok */
    __shared__ float    w2s[HDIM];
    __shared__ float    colbuf[8][32];

    const int jh = blockIdx.x, ih = blockIdx.y, b = blockIdx.z;
    const int tid = threadIdx.x, lane = tid & 31, w = tid >> 5;

    if (tid < 64) *(float4*)&w2s[tid * 4] = *(const float4*)(W2 + tid * 4);

    /* s1: 16 rows x 128 half2 = 512 uint4 (2/thread) */
    const unsigned* s1g = g_sh + (b * NATOMS + ih * 16) * H2;
#pragma unroll
    for (int l = 0; l < 2; l++) {
        int f = tid + l * 256;
        *(uint4*)&s1s[f * 4] = *(const uint4*)(s1g + f * 4);
    }
    /* s2: 32 rows x 128 half2, pad-130 rows, uint2 stores (8B aligned) */
    const unsigned* s2g = g_sh + (BATCH * NATOMS + b * NATOMS + jh * 32) * H2;
#pragma unroll
    for (int l = 0; l < 4; l++) {
        int f = tid + l * 256;
        int j = f >> 5, q = f & 31;
        uint4 v = *(const uint4*)(s2g + f * 4);
        unsigned* d = &s2s[j * 130 + q * 4];
        *(uint2*)&d[0] = make_uint2(v.x, v.y);
        *(uint2*)&d[2] = make_uint2(v.z, v.w);
    }
    __syncthreads();

    const unsigned* s2row = &s2s[lane * 130];
    float acc0[2], acc1[2];
    acc0[0] = acc0[1] = acc1[0] = acc1[1] = 0.f;

#pragma unroll 4
    for (int hp = 0; hp < 64; hp++) {
        float4 wv = *(const float4*)&w2s[hp * 4];      /* h values 4hp..4hp+3 */
        uint2 b2 = *(const uint2*)&s2row[hp * 2];      /* 2 half2             */
#pragma unroll
        for (int ii = 0; ii < 2; ii++) {
            uint2 a2 = *(const uint2*)&s1s[(w * 2 + ii) * 128 + hp * 2];
            unsigned t0 = tanh2u(hadd2u(a2.x, b2.x));
            unsigned t1 = tanh2u(hadd2u(a2.y, b2.y));
            float2 f0 = __half22float2(u2h(t0));
            float2 f1 = __half22float2(u2h(t1));
            float* acc = ii ? acc1 : acc0;
            acc[0] = fmaf(wv.x, f0.x, acc[0]);
            acc[1] = fmaf(wv.y, f0.y, acc[1]);
            acc[0] = fmaf(wv.z, f1.x, acc[0]);
            acc[1] = fmaf(wv.w, f1.y, acc[1]);
        }
    }

    float colacc = 0.f;
#pragma unroll
    for (int ii = 0; ii < 2; ii++) {
        float* acc = ii ? acc1 : acc0;
        float e = __expf(acc[0] + acc[1]);   /* bounded scores: no max pass */
        colacc += e;
        float rs = e;
#pragma unroll
        for (int o = 16; o > 0; o >>= 1)
            rs += __shfl_xor_sync(0xffffffffu, rs, o);
        if (lane == 0)
            g_rp[(b * NATOMS + ih * 16 + w * 2 + ii) * 2 + jh] = rs;
    }
    colbuf[w][lane] = colacc;
    __syncthreads();
    if (tid < 32) {
        float s = 0.f;
#pragma unroll
        for (int ww = 0; ww < 8; ww++) s += colbuf[ww][tid];
        g_cp[(b * NATOMS + jh * 32 + tid) * 4 + ih] = s;
    }
}

/* ---------------- normalize ---------------- */
__global__ void __launch_bounds__(64) finalize_kernel(float* __restrict__ out)
{
    int b = blockIdx.x, i = threadIdx.x;
    float r = g_rp[(b * 64 + i) * 2] + g_rp[(b * 64 + i) * 2 + 1];
    const float* cp = &g_cp[(b * 64 + i) * 4];
    float c = (cp[0] + cp[1]) + (cp[2] + cp[3]);
    __shared__ float red[64];
    red[i] = r;
    __syncthreads();
    if (i < 32) {
        float v = red[i] + red[i + 32];
#pragma unroll
        for (int o = 16; o > 0; o >>= 1)
            v += __shfl_xor_sync(0xffffffffu, v, o);
        if (i == 0) red[0] = v;
    }
    __syncthreads();
    float inv = 1.f / red[0];
    out[b * 64 + i] = r * inv;
    out[BATCH * NATOMS + b * 64 + i] = c * inv;
}

extern "C" void kernel_launch(void* const* d_in, const int* in_sizes, int n_in,
                              void* d_out, int out_size)
{
    const float *h1 = nullptr, *h2 = nullptr, *W1 = nullptr,
                *b1 = nullptr, *W2 = nullptr;
    for (int idx = 0; idx < n_in; idx++) {
        int sz = in_sizes[idx];
        if (sz == BATCH * NATOMS * HDIM) {
            if (!h1) h1 = (const float*)d_in[idx];
            else if (!h2) h2 = (const float*)d_in[idx];
        } else if (sz == 2 * HDIM * HDIM) {
            W1 = (const float*)d_in[idx];
        } else if (sz == HDIM) {
            if (!b1) b1 = (const float*)d_in[idx];
            else if (!W2) W2 = (const float*)d_in[idx];
        }
    }
    float* out = (float*)d_out;

    gemm_kernel<<<dim3(NROWS / 64, HDIM / 64), 128>>>(h1, h2, W1, b1);
    score_kernel<<<dim3(2, 4, BATCH), 256>>>(W2);
    finalize_kernel<<<BATCH, 64>>>(out);
}